// round 1
// baseline (speedup 1.0000x reference)
#include <cuda_runtime.h>

#define N_PTS 8192
#define D_TOK 384
#define KNN_K 16
#define KIN   387          // D_TOK + 3
#define KPAD  400          // padded K (multiple of 16)
#define NOUT  768          // [a | b] concatenated outputs
#define NCH   8
#define CHUNK (N_PTS / NCH)   // 1024

#define FLT_BIG 3.402823e38f

// ---------------- scratch (allocation-free rule: __device__ globals) --------
__device__ float g_Xp[N_PTS * KPAD];        // 13.1 MB padded node features
__device__ float g_Wp[KPAD * NOUT];         //  1.2 MB packed [W1_top | W1_bot]
__device__ float g_C [N_PTS * NOUT];        // 25.2 MB [a_i | b_i]
__device__ int   g_knn[N_PTS * KNN_K];
__device__ float g_pd[N_PTS * NCH * KNN_K];
__device__ int   g_pi[N_PTS * NCH * KNN_K];

// ---------------- pack kernels ---------------------------------------------
__global__ void pack_x(const float* __restrict__ token, const float* __restrict__ xyz)
{
    int i = blockIdx.x;
    for (int k = threadIdx.x; k < KPAD; k += blockDim.x) {
        float v;
        if (k < D_TOK)        v = token[i * D_TOK + k];
        else if (k < KIN)     v = xyz[i * 3 + (k - D_TOK)];
        else                  v = 0.f;
        g_Xp[i * KPAD + k] = v;
    }
}

__global__ void pack_w(const float* __restrict__ W1)
{
    int k = blockIdx.x;
    for (int n = threadIdx.x; n < NOUT; n += blockDim.x) {
        float v = 0.f;
        if (k < KIN) {
            if (n < D_TOK) v = W1[k * D_TOK + n];
            else           v = W1[(KIN + k) * D_TOK + (n - D_TOK)];
        }
        g_Wp[k * NOUT + n] = v;
    }
}

// ---------------- KNN -------------------------------------------------------
#define KNN_INSERT(dval, jval)                                              \
    do {                                                                    \
        if ((dval) < dmax) {                                                \
            _Pragma("unroll")                                               \
            for (int s_ = 0; s_ < KNN_K; s_++)                              \
                if (s_ == maxslot) { kd[s_] = (dval); ki[s_] = (jval); }    \
            dmax = -FLT_BIG; maxslot = 0;                                   \
            _Pragma("unroll")                                               \
            for (int s_ = 0; s_ < KNN_K; s_++)                              \
                if (kd[s_] > dmax) { dmax = kd[s_]; maxslot = s_; }         \
        }                                                                   \
    } while (0)

__global__ void knn_partial(const float* __restrict__ xyz)
{
    __shared__ float sx[256], sy[256], sz[256], sq[256];
    int q     = blockIdx.x * 256 + threadIdx.x;
    int chunk = blockIdx.y;

    float xi = xyz[3 * q], yi = xyz[3 * q + 1], zi = xyz[3 * q + 2];
    float sqi = xi * xi + yi * yi + zi * zi;
    float nx = -2.f * xi, ny = -2.f * yi, nz = -2.f * zi;

    float kd[KNN_K]; int ki[KNN_K];
    #pragma unroll
    for (int s = 0; s < KNN_K; s++) { kd[s] = FLT_BIG; ki[s] = 0; }
    float dmax = FLT_BIG; int maxslot = 0;

    int base = chunk * CHUNK;
    for (int t0 = 0; t0 < CHUNK; t0 += 256) {
        int j = base + t0 + threadIdx.x;
        __syncthreads();
        float px = xyz[3 * j], py = xyz[3 * j + 1], pz = xyz[3 * j + 2];
        sx[threadIdx.x] = px; sy[threadIdx.x] = py; sz[threadIdx.x] = pz;
        sq[threadIdx.x] = px * px + py * py + pz * pz;
        __syncthreads();

        for (int c = 0; c < 256; c++) {
            int jj = base + t0 + c;
            float d = sqi + sq[c];
            d = fmaf(nx, sx[c], d);
            d = fmaf(ny, sy[c], d);
            d = fmaf(nz, sz[c], d);
            if (jj != q) KNN_INSERT(d, jj);
        }
    }
    int ob = (q * NCH + chunk) * KNN_K;
    #pragma unroll
    for (int s = 0; s < KNN_K; s++) { g_pd[ob + s] = kd[s]; g_pi[ob + s] = ki[s]; }
}

__global__ void knn_merge()
{
    int q = blockIdx.x * blockDim.x + threadIdx.x;
    float kd[KNN_K]; int ki[KNN_K];
    #pragma unroll
    for (int s = 0; s < KNN_K; s++) { kd[s] = FLT_BIG; ki[s] = 0; }
    float dmax = FLT_BIG; int maxslot = 0;

    int ob = q * NCH * KNN_K;
    for (int e = 0; e < NCH * KNN_K; e++) {
        float d = g_pd[ob + e];
        int   j = g_pi[ob + e];
        KNN_INSERT(d, j);
    }
    #pragma unroll
    for (int s = 0; s < KNN_K; s++) g_knn[q * KNN_K + s] = ki[s];
}

// ---------------- node GEMM: C[8192,768] = Xp @ Wp (+b1 on first 384) ------
__global__ __launch_bounds__(256, 2) void gemm_kernel(const float* __restrict__ b1)
{
    __shared__ float As[2][16][132];   // [k][m], padded
    __shared__ float Bs[2][16][128];   // [k][n]

    int tid = threadIdx.x;
    int bm = blockIdx.y, bn = blockIdx.x;

    const float* Ab = g_Xp + bm * 128 * KPAD;
    const float* Bb = g_Wp + bn * 128;

    int aRow = tid >> 2, aCol = (tid & 3) << 2;      // A: 128 rows x 16 cols
    int bRow = tid >> 5, bCol = (tid & 31) << 2;     // B: 16 rows x 128 cols
    int ty = tid >> 4, tx = tid & 15;

    float acc[8][8];
    #pragma unroll
    for (int i = 0; i < 8; i++)
        #pragma unroll
        for (int j = 0; j < 8; j++) acc[i][j] = 0.f;

    auto loadTiles = [&](int buf, int k0) {
        #pragma unroll
        for (int r = 0; r < 2; r++) {
            float4 v = *(const float4*)(Ab + (aRow + 64 * r) * KPAD + k0 + aCol);
            As[buf][aCol + 0][aRow + 64 * r] = v.x;
            As[buf][aCol + 1][aRow + 64 * r] = v.y;
            As[buf][aCol + 2][aRow + 64 * r] = v.z;
            As[buf][aCol + 3][aRow + 64 * r] = v.w;
        }
        #pragma unroll
        for (int r = 0; r < 2; r++) {
            float4 v = *(const float4*)(Bb + (k0 + bRow + 8 * r) * NOUT + bCol);
            *(float4*)&Bs[buf][bRow + 8 * r][bCol] = v;
        }
    };

    loadTiles(0, 0);
    __syncthreads();

    const int NT = KPAD / 16;   // 25
    for (int t = 0; t < NT; t++) {
        if (t + 1 < NT) loadTiles((t + 1) & 1, (t + 1) * 16);
        int cb = t & 1;
        #pragma unroll
        for (int k = 0; k < 16; k++) {
            float rm[8], rn[8];
            *(float4*)&rm[0] = *(const float4*)&As[cb][k][ty * 8];
            *(float4*)&rm[4] = *(const float4*)&As[cb][k][ty * 8 + 4];
            *(float4*)&rn[0] = *(const float4*)&Bs[cb][k][tx * 8];
            *(float4*)&rn[4] = *(const float4*)&Bs[cb][k][tx * 8 + 4];
            #pragma unroll
            for (int i = 0; i < 8; i++)
                #pragma unroll
                for (int j = 0; j < 8; j++)
                    acc[i][j] = fmaf(rm[i], rn[j], acc[i][j]);
        }
        __syncthreads();
    }

    // epilogue: bias only on columns < 384 (bn < 3 — whole-block uniform)
    int colBase = bn * 128 + tx * 8;
    int rowBase = bm * 128 + ty * 8;
    float bias[8];
    bool hasB = (bn < 3);
    #pragma unroll
    for (int j = 0; j < 8; j++) bias[j] = hasB ? b1[colBase + j] : 0.f;

    #pragma unroll
    for (int i = 0; i < 8; i++) {
        float4 o0 = make_float4(acc[i][0] + bias[0], acc[i][1] + bias[1],
                                acc[i][2] + bias[2], acc[i][3] + bias[3]);
        float4 o1 = make_float4(acc[i][4] + bias[4], acc[i][5] + bias[5],
                                acc[i][6] + bias[6], acc[i][7] + bias[7]);
        float* Cp = g_C + (rowBase + i) * NOUT + colBase;
        *(float4*)(Cp)     = o0;
        *(float4*)(Cp + 4) = o1;
    }
}

// ---------------- edge kernel: one warp per node ----------------------------
__global__ __launch_bounds__(256) void edge_kernel(const float* __restrict__ xyz,
                                                   const float* __restrict__ W2,
                                                   const float* __restrict__ b2,
                                                   float* __restrict__ out)
{
    int gwarp = (blockIdx.x * blockDim.x + threadIdx.x) >> 5;
    int lane  = threadIdx.x & 31;
    if (gwarp >= N_PTS) return;

    const float* Ci = g_C + gwarp * NOUT;

    float4 s[3];
    float w2[12][3];
    #pragma unroll
    for (int dn = 0; dn < 3; dn++) {
        int dim0 = lane * 4 + dn * 128;
        float4 a = *(const float4*)(Ci + dim0);           // a_i (has b1)
        float4 b = *(const float4*)(Ci + D_TOK + dim0);   // b_i
        s[dn] = make_float4(a.x - b.x, a.y - b.y, a.z - b.z, a.w - b.w);
        #pragma unroll
        for (int u = 0; u < 4; u++)
            #pragma unroll
            for (int c = 0; c < 3; c++)
                w2[dn * 4 + u][c] = W2[(dim0 + u) * 3 + c];
    }

    float acc0 = 0.f, acc1 = 0.f, acc2 = 0.f;
    #pragma unroll 4
    for (int j = 0; j < KNN_K; j++) {
        int nj = g_knn[gwarp * KNN_K + j];
        const float* Bj = g_C + nj * NOUT + D_TOK;
        #pragma unroll
        for (int dn = 0; dn < 3; dn++) {
            float4 b = *(const float4*)(Bj + lane * 4 + dn * 128);
            float h;
            h = fmaxf(s[dn].x + b.x, 0.f);
            acc0 = fmaf(h, w2[dn*4+0][0], acc0); acc1 = fmaf(h, w2[dn*4+0][1], acc1); acc2 = fmaf(h, w2[dn*4+0][2], acc2);
            h = fmaxf(s[dn].y + b.y, 0.f);
            acc0 = fmaf(h, w2[dn*4+1][0], acc0); acc1 = fmaf(h, w2[dn*4+1][1], acc1); acc2 = fmaf(h, w2[dn*4+1][2], acc2);
            h = fmaxf(s[dn].z + b.z, 0.f);
            acc0 = fmaf(h, w2[dn*4+2][0], acc0); acc1 = fmaf(h, w2[dn*4+2][1], acc1); acc2 = fmaf(h, w2[dn*4+2][2], acc2);
            h = fmaxf(s[dn].w + b.w, 0.f);
            acc0 = fmaf(h, w2[dn*4+3][0], acc0); acc1 = fmaf(h, w2[dn*4+3][1], acc1); acc2 = fmaf(h, w2[dn*4+3][2], acc2);
        }
    }

    #pragma unroll
    for (int off = 16; off > 0; off >>= 1) {
        acc0 += __shfl_down_sync(0xFFFFFFFFu, acc0, off);
        acc1 += __shfl_down_sync(0xFFFFFFFFu, acc1, off);
        acc2 += __shfl_down_sync(0xFFFFFFFFu, acc2, off);
    }

    if (lane == 0) {
        const float inv = 1.f / 16.f;
        out[gwarp * 3 + 0] = xyz[gwarp * 3 + 0] + acc0 * inv + b2[0];
        out[gwarp * 3 + 1] = xyz[gwarp * 3 + 1] + acc1 * inv + b2[1];
        out[gwarp * 3 + 2] = xyz[gwarp * 3 + 2] + acc2 * inv + b2[2];
    }
}

// ---------------- launch ----------------------------------------------------
extern "C" void kernel_launch(void* const* d_in, const int* in_sizes, int n_in,
                              void* d_out, int out_size)
{
    const float* xyz   = (const float*)d_in[0];
    const float* token = (const float*)d_in[1];
    const float* W1    = (const float*)d_in[2];
    const float* b1    = (const float*)d_in[3];
    const float* W2    = (const float*)d_in[4];
    const float* b2    = (const float*)d_in[5];
    float* out = (float*)d_out;

    pack_x<<<N_PTS, 128>>>(token, xyz);
    pack_w<<<KPAD, 256>>>(W1);
    knn_partial<<<dim3(N_PTS / 256, NCH), 256>>>(xyz);
    knn_merge<<<N_PTS / 256, 256>>>();
    gemm_kernel<<<dim3(NOUT / 128, N_PTS / 128), 256>>>(b1);
    edge_kernel<<<N_PTS / 8, 256>>>(xyz, W2, b2, out);
}

// round 3
// speedup vs baseline: 1.0986x; 1.0986x over previous
#include <cuda_runtime.h>

#define N_PTS 8192
#define D_TOK 384
#define KNN_K 16
#define KIN   387          // D_TOK + 3
#define KPAD  400          // padded K (multiple of 16)
#define NOUT  768          // [a | b] concatenated outputs
#define NCH   4
#define CHUNK (N_PTS / NCH)   // 2048

#define FLT_BIG 3.402823e38f

typedef unsigned long long u64;

// ---------------- scratch (allocation-free rule: __device__ globals) --------
__device__ float g_Xp[N_PTS * KPAD];        // 13.1 MB padded node features
__device__ float g_Wp[KPAD * NOUT];         //  1.2 MB packed [W1_top | W1_bot]
__device__ float g_C [N_PTS * NOUT];        // 25.2 MB [a_i | b_i]
__device__ int   g_knn[N_PTS * KNN_K];
__device__ float g_pd[N_PTS * NCH * KNN_K];
__device__ int   g_pi[N_PTS * NCH * KNN_K];

// ---------------- f32x2 helpers (Blackwell packed fp32) ---------------------
__device__ __forceinline__ void ffma2(u64& c, u64 a, u64 b) {
    asm("fma.rn.f32x2 %0, %1, %2, %0;" : "+l"(c) : "l"(a), "l"(b));
}
__device__ __forceinline__ u64 pack2(float x) {
    u64 r; unsigned u = __float_as_uint(x);
    asm("mov.b64 %0, {%1, %1};" : "=l"(r) : "r"(u));
    return r;
}
__device__ __forceinline__ float lo32(u64 v) { return __uint_as_float((unsigned)v); }
__device__ __forceinline__ float hi32(u64 v) { return __uint_as_float((unsigned)(v >> 32)); }

// ---------------- pack kernels ---------------------------------------------
__global__ void pack_x(const float* __restrict__ token, const float* __restrict__ xyz)
{
    int i = blockIdx.x;
    for (int k = threadIdx.x; k < KPAD; k += blockDim.x) {
        float v;
        if (k < D_TOK)        v = token[i * D_TOK + k];
        else if (k < KIN)     v = xyz[i * 3 + (k - D_TOK)];
        else                  v = 0.f;
        g_Xp[i * KPAD + k] = v;
    }
}

__global__ void pack_w(const float* __restrict__ W1)
{
    int k = blockIdx.x;
    for (int n = threadIdx.x; n < NOUT; n += blockDim.x) {
        float v = 0.f;
        if (k < KIN) {
            if (n < D_TOK) v = W1[k * D_TOK + n];
            else           v = W1[(KIN + k) * D_TOK + (n - D_TOK)];
        }
        g_Wp[k * NOUT + n] = v;
    }
}

// ---------------- KNN -------------------------------------------------------
#define KNN_INSERT(dval, jval)                                              \
    do {                                                                    \
        if ((dval) < dmax) {                                                \
            _Pragma("unroll")                                               \
            for (int s_ = 0; s_ < KNN_K; s_++)                              \
                if (s_ == maxslot) { kd[s_] = (dval); ki[s_] = (jval); }    \
            dmax = -FLT_BIG; maxslot = 0;                                   \
            _Pragma("unroll")                                               \
            for (int s_ = 0; s_ < KNN_K; s_++)                              \
                if (kd[s_] > dmax) { dmax = kd[s_]; maxslot = s_; }         \
        }                                                                   \
    } while (0)

__global__ __launch_bounds__(128) void knn_partial(const float* __restrict__ xyz)
{
    __shared__ float sx[128], sy[128], sz[128], sq[128];
    int q     = blockIdx.x * 128 + threadIdx.x;
    int chunk = blockIdx.y;

    float xi = xyz[3 * q], yi = xyz[3 * q + 1], zi = xyz[3 * q + 2];
    float sqi = xi * xi + yi * yi + zi * zi;
    float nx = -2.f * xi, ny = -2.f * yi, nz = -2.f * zi;

    float kd[KNN_K]; int ki[KNN_K];
    #pragma unroll
    for (int s = 0; s < KNN_K; s++) { kd[s] = FLT_BIG; ki[s] = 0; }
    float dmax = FLT_BIG; int maxslot = 0;

    int base = chunk * CHUNK;
    for (int t0 = 0; t0 < CHUNK; t0 += 128) {
        int j = base + t0 + threadIdx.x;
        __syncthreads();
        float px = xyz[3 * j], py = xyz[3 * j + 1], pz = xyz[3 * j + 2];
        sx[threadIdx.x] = px; sy[threadIdx.x] = py; sz[threadIdx.x] = pz;
        sq[threadIdx.x] = px * px + py * py + pz * pz;
        __syncthreads();

        for (int c = 0; c < 128; c++) {
            int jj = base + t0 + c;
            float d = sqi + sq[c];
            d = fmaf(nx, sx[c], d);
            d = fmaf(ny, sy[c], d);
            d = fmaf(nz, sz[c], d);
            if (jj != q) KNN_INSERT(d, jj);
        }
    }
    int ob = (q * NCH + chunk) * KNN_K;
    #pragma unroll
    for (int s = 0; s < KNN_K; s++) { g_pd[ob + s] = kd[s]; g_pi[ob + s] = ki[s]; }
}

// warp-per-query merge: 64 candidate keys -> top-16 via min-extraction
__global__ __launch_bounds__(256) void knn_merge()
{
    int warp = (blockIdx.x * blockDim.x + threadIdx.x) >> 5;
    int lane = threadIdx.x & 31;
    const int E   = NCH * KNN_K;     // 64
    const int PER = E / 32;          // 2

    u64 key[PER];
    int ob = warp * E;
    #pragma unroll
    for (int t = 0; t < PER; t++) {
        int e = lane + 32 * t;
        float d = fmaxf(g_pd[ob + e], 0.f);     // guard: keep bits-order == value-order
        unsigned idx = (unsigned)g_pi[ob + e];
        key[t] = ((u64)__float_as_uint(d) << 32) | idx;
    }

    int myidx = 0;
    #pragma unroll
    for (int r = 0; r < KNN_K; r++) {
        u64 m = key[0];
        #pragma unroll
        for (int t = 1; t < PER; t++) m = (key[t] < m) ? key[t] : m;
        #pragma unroll
        for (int off = 16; off > 0; off >>= 1) {
            u64 o = __shfl_xor_sync(0xFFFFFFFFu, m, off);
            m = (o < m) ? o : m;
        }
        if (r == lane) myidx = (int)(unsigned)(m & 0xFFFFFFFFull);
        #pragma unroll
        for (int t = 0; t < PER; t++)
            if (key[t] == m) key[t] = ~0ull;
    }
    if (lane < KNN_K) g_knn[warp * KNN_K + lane] = myidx;
}

// ---------------- node GEMM: C[8192,768] = Xp @ Wp (+b1 on first 384) ------
// inner product via packed fma.rn.f32x2 (2 fp32 FMA / instruction)
__global__ __launch_bounds__(256, 2) void gemm_kernel(const float* __restrict__ b1)
{
    __shared__ float As[2][16][132];   // [k][m], padded
    __shared__ float Bs[2][16][128];   // [k][n]

    int tid = threadIdx.x;
    int bm = blockIdx.y, bn = blockIdx.x;

    const float* Ab = g_Xp + bm * 128 * KPAD;
    const float* Bb = g_Wp + bn * 128;

    int aRow = tid >> 2, aCol = (tid & 3) << 2;      // A: 128 rows x 16 cols
    int bRow = tid >> 5, bCol = (tid & 31) << 2;     // B: 16 rows x 128 cols
    int ty = tid >> 4, tx = tid & 15;

    u64 acc[8][4];
    #pragma unroll
    for (int i = 0; i < 8; i++)
        #pragma unroll
        for (int j = 0; j < 4; j++) acc[i][j] = 0ull;

    auto loadTiles = [&](int buf, int k0) {
        #pragma unroll
        for (int r = 0; r < 2; r++) {
            float4 v = *(const float4*)(Ab + (aRow + 64 * r) * KPAD + k0 + aCol);
            As[buf][aCol + 0][aRow + 64 * r] = v.x;
            As[buf][aCol + 1][aRow + 64 * r] = v.y;
            As[buf][aCol + 2][aRow + 64 * r] = v.z;
            As[buf][aCol + 3][aRow + 64 * r] = v.w;
        }
        #pragma unroll
        for (int r = 0; r < 2; r++) {
            float4 v = *(const float4*)(Bb + (k0 + bRow + 8 * r) * NOUT + bCol);
            *(float4*)&Bs[buf][bRow + 8 * r][bCol] = v;
        }
    };

    loadTiles(0, 0);
    __syncthreads();

    const int NT = KPAD / 16;   // 25
    for (int t = 0; t < NT; t++) {
        if (t + 1 < NT) loadTiles((t + 1) & 1, (t + 1) * 16);
        int cb = t & 1;
        #pragma unroll
        for (int k = 0; k < 16; k++) {
            float rm[8];
            *(float4*)&rm[0] = *(const float4*)&As[cb][k][ty * 8];
            *(float4*)&rm[4] = *(const float4*)&As[cb][k][ty * 8 + 4];
            u64 rn[4];
            {
                ulonglong2 p0 = *(const ulonglong2*)&Bs[cb][k][tx * 8];
                ulonglong2 p1 = *(const ulonglong2*)&Bs[cb][k][tx * 8 + 4];
                rn[0] = p0.x; rn[1] = p0.y; rn[2] = p1.x; rn[3] = p1.y;
            }
            #pragma unroll
            for (int i = 0; i < 8; i++) {
                u64 a2 = pack2(rm[i]);
                #pragma unroll
                for (int j = 0; j < 4; j++)
                    ffma2(acc[i][j], a2, rn[j]);
            }
        }
        __syncthreads();
    }

    // epilogue: bias only on columns < 384 (bn < 3 — whole-block uniform)
    int colBase = bn * 128 + tx * 8;
    int rowBase = bm * 128 + ty * 8;
    float bias[8];
    bool hasB = (bn < 3);
    #pragma unroll
    for (int j = 0; j < 8; j++) bias[j] = hasB ? b1[colBase + j] : 0.f;

    #pragma unroll
    for (int i = 0; i < 8; i++) {
        float4 o0 = make_float4(lo32(acc[i][0]) + bias[0], hi32(acc[i][0]) + bias[1],
                                lo32(acc[i][1]) + bias[2], hi32(acc[i][1]) + bias[3]);
        float4 o1 = make_float4(lo32(acc[i][2]) + bias[4], hi32(acc[i][2]) + bias[5],
                                lo32(acc[i][3]) + bias[6], hi32(acc[i][3]) + bias[7]);
        float* Cp = g_C + (rowBase + i) * NOUT + colBase;
        *(float4*)(Cp)     = o0;
        *(float4*)(Cp + 4) = o1;
    }
}

// ---------------- edge kernel: one warp per node ----------------------------
__global__ __launch_bounds__(256) void edge_kernel(const float* __restrict__ xyz,
                                                   const float* __restrict__ W2,
                                                   const float* __restrict__ b2,
                                                   float* __restrict__ out)
{
    int gwarp = (blockIdx.x * blockDim.x + threadIdx.x) >> 5;
    int lane  = threadIdx.x & 31;
    if (gwarp >= N_PTS) return;

    const float* Ci = g_C + gwarp * NOUT;

    float4 s[3];
    float w2[12][3];
    #pragma unroll
    for (int dn = 0; dn < 3; dn++) {
        int dim0 = lane * 4 + dn * 128;
        float4 a = *(const float4*)(Ci + dim0);           // a_i (has b1)
        float4 b = *(const float4*)(Ci + D_TOK + dim0);   // b_i
        s[dn] = make_float4(a.x - b.x, a.y - b.y, a.z - b.z, a.w - b.w);
        #pragma unroll
        for (int u = 0; u < 4; u++)
            #pragma unroll
            for (int c = 0; c < 3; c++)
                w2[dn * 4 + u][c] = W2[(dim0 + u) * 3 + c];
    }

    float acc0 = 0.f, acc1 = 0.f, acc2 = 0.f;
    #pragma unroll 4
    for (int j = 0; j < KNN_K; j++) {
        int nj = g_knn[gwarp * KNN_K + j];
        const float* Bj = g_C + nj * NOUT + D_TOK;
        #pragma unroll
        for (int dn = 0; dn < 3; dn++) {
            float4 b = *(const float4*)(Bj + lane * 4 + dn * 128);
            float h;
            h = fmaxf(s[dn].x + b.x, 0.f);
            acc0 = fmaf(h, w2[dn*4+0][0], acc0); acc1 = fmaf(h, w2[dn*4+0][1], acc1); acc2 = fmaf(h, w2[dn*4+0][2], acc2);
            h = fmaxf(s[dn].y + b.y, 0.f);
            acc0 = fmaf(h, w2[dn*4+1][0], acc0); acc1 = fmaf(h, w2[dn*4+1][1], acc1); acc2 = fmaf(h, w2[dn*4+1][2], acc2);
            h = fmaxf(s[dn].z + b.z, 0.f);
            acc0 = fmaf(h, w2[dn*4+2][0], acc0); acc1 = fmaf(h, w2[dn*4+2][1], acc1); acc2 = fmaf(h, w2[dn*4+2][2], acc2);
            h = fmaxf(s[dn].w + b.w, 0.f);
            acc0 = fmaf(h, w2[dn*4+3][0], acc0); acc1 = fmaf(h, w2[dn*4+3][1], acc1); acc2 = fmaf(h, w2[dn*4+3][2], acc2);
        }
    }

    #pragma unroll
    for (int off = 16; off > 0; off >>= 1) {
        acc0 += __shfl_down_sync(0xFFFFFFFFu, acc0, off);
        acc1 += __shfl_down_sync(0xFFFFFFFFu, acc1, off);
        acc2 += __shfl_down_sync(0xFFFFFFFFu, acc2, off);
    }

    if (lane == 0) {
        const float inv = 1.f / 16.f;
        out[gwarp * 3 + 0] = xyz[gwarp * 3 + 0] + acc0 * inv + b2[0];
        out[gwarp * 3 + 1] = xyz[gwarp * 3 + 1] + acc1 * inv + b2[1];
        out[gwarp * 3 + 2] = xyz[gwarp * 3 + 2] + acc2 * inv + b2[2];
    }
}

// ---------------- launch ----------------------------------------------------
extern "C" void kernel_launch(void* const* d_in, const int* in_sizes, int n_in,
                              void* d_out, int out_size)
{
    const float* xyz   = (const float*)d_in[0];
    const float* token = (const float*)d_in[1];
    const float* W1    = (const float*)d_in[2];
    const float* b1    = (const float*)d_in[3];
    const float* W2    = (const float*)d_in[4];
    const float* b2    = (const float*)d_in[5];
    float* out = (float*)d_out;

    pack_x<<<N_PTS, 128>>>(token, xyz);
    pack_w<<<KPAD, 256>>>(W1);
    knn_partial<<<dim3(N_PTS / 128, NCH), 128>>>(xyz);
    knn_merge<<<(N_PTS * 32) / 256, 256>>>();
    gemm_kernel<<<dim3(NOUT / 128, N_PTS / 128), 256>>>(b1);
    edge_kernel<<<N_PTS / 8, 256>>>(xyz, W2, b2, out);
}